// round 1
// baseline (speedup 1.0000x reference)
#include <cuda_runtime.h>
#include <math.h>

// Problem constants: B=8, S=4096, D=1024, H=16, hd=64
#define MM 32768          // B*S rows
#define DD 1024
#define N_QKV 3072        // 3*D
#define NHEAD 16
#define HDIM 64

// Scratch (device globals: allowed; no runtime allocation)
__device__ float g_qkv[(size_t)MM * N_QKV];   // 402 MB
__device__ float g_val[(size_t)MM * DD];      // 134 MB

// ---------------------------------------------------------------------------
// SGEMM with bias: C[M,N] = A[M,K] @ B[K,N] + bias[N]
// 128x128 block tile, BK=8, 256 threads, 8x8 per thread.
// M,N,K assumed multiples of 128/128/8 (true here: 32768, 3072/1024, 1024).
// ---------------------------------------------------------------------------
__global__ __launch_bounds__(256, 2)
void sgemm_bias_kernel(const float* __restrict__ A,
                       const float* __restrict__ B,
                       const float* __restrict__ bias,
                       float* __restrict__ C,
                       int N, int K)
{
    const int BM = 128, BN = 128, BK = 8;
    __shared__ float As[BK][BM];
    __shared__ float Bs[BK][BN];

    const int tid = threadIdx.x;
    const int bx = blockIdx.x;          // N tile
    const int by = blockIdx.y;          // M tile

    const float* Ab = A + (size_t)by * BM * K;
    const float* Bb = B + (size_t)bx * BN;

    const int irA = tid >> 1;           // 0..127
    const int icA = (tid & 1) * 4;      // 0 or 4
    const int irB = tid >> 5;           // 0..7
    const int icB = (tid & 31) * 4;     // 0..124

    const int tRow = tid >> 4;          // 0..15
    const int tCol = tid & 15;          // 0..15

    float acc[8][8];
    #pragma unroll
    for (int i = 0; i < 8; i++)
        #pragma unroll
        for (int j = 0; j < 8; j++) acc[i][j] = 0.0f;

    float regM[8], regN[8];

    for (int k0 = 0; k0 < K; k0 += BK) {
        // load A tile (transpose into As[k][m])
        float4 a4 = *reinterpret_cast<const float4*>(Ab + (size_t)irA * K + k0 + icA);
        As[icA + 0][irA] = a4.x;
        As[icA + 1][irA] = a4.y;
        As[icA + 2][irA] = a4.z;
        As[icA + 3][irA] = a4.w;
        // load B tile
        float4 b4 = *reinterpret_cast<const float4*>(Bb + (size_t)(k0 + irB) * N + icB);
        *reinterpret_cast<float4*>(&Bs[irB][icB]) = b4;
        __syncthreads();

        #pragma unroll
        for (int k = 0; k < BK; k++) {
            #pragma unroll
            for (int i = 0; i < 8; i++) regM[i] = As[k][tRow * 8 + i];
            #pragma unroll
            for (int j = 0; j < 8; j++) regN[j] = Bs[k][tCol * 8 + j];
            #pragma unroll
            for (int i = 0; i < 8; i++)
                #pragma unroll
                for (int j = 0; j < 8; j++)
                    acc[i][j] += regM[i] * regN[j];
        }
        __syncthreads();
    }

    // epilogue: add bias, store
    float bvals[8];
    #pragma unroll
    for (int j = 0; j < 8; j++) bvals[j] = bias[bx * BN + tCol * 8 + j];

    #pragma unroll
    for (int i = 0; i < 8; i++) {
        size_t row = (size_t)by * BM + tRow * 8 + i;
        float* Crow = C + row * N + bx * BN + tCol * 8;
        float4 o0, o1;
        o0.x = acc[i][0] + bvals[0];
        o0.y = acc[i][1] + bvals[1];
        o0.z = acc[i][2] + bvals[2];
        o0.w = acc[i][3] + bvals[3];
        o1.x = acc[i][4] + bvals[4];
        o1.y = acc[i][5] + bvals[5];
        o1.z = acc[i][6] + bvals[6];
        o1.w = acc[i][7] + bvals[7];
        *reinterpret_cast<float4*>(Crow + 0) = o0;
        *reinterpret_cast<float4*>(Crow + 4) = o1;
    }
}

// ---------------------------------------------------------------------------
// Per-position head attention. One block (256 threads) per token position p.
// qkv row layout: [h (16)][q 0:64 | k 64:128 | v 128:192]
// scores[i][j] = (1/8) * dot(q_i, k_j); softmax over j; out_i = sum_j a_ij v_j
// Output row layout: [h (16)][d (64)] = D=1024 floats.
// ---------------------------------------------------------------------------
__global__ __launch_bounds__(256)
void attn_kernel()
{
    __shared__ float sq[NHEAD][HDIM];       // 16x64
    __shared__ float skT[HDIM][NHEAD];      // 64x16 (transposed: conflict-free)
    __shared__ float sv[NHEAD][HDIM];       // 16x64
    __shared__ float sat[NHEAD][NHEAD];     // 16x16 attention weights

    const size_t p = blockIdx.x;
    const float* row = g_qkv + p * (size_t)N_QKV;
    const int tid = threadIdx.x;

    // load 3072 floats, scatter to q / kT / v
    for (int idx = tid; idx < N_QKV; idx += 256) {
        float v = row[idx];
        int h = idx / 192;
        int r = idx - h * 192;
        if (r < 64)        sq[h][r] = v;
        else if (r < 128)  skT[r - 64][h] = v;
        else               sv[h][r - 128] = v;
    }
    __syncthreads();

    // one thread per (i,j) score; rows of 16 live in 16-lane shuffle groups
    const int i = tid >> 4;
    const int j = tid & 15;
    float s = 0.0f;
    #pragma unroll 8
    for (int d = 0; d < HDIM; d++) s += sq[i][d] * skT[d][j];
    s *= 0.125f;   // 1/sqrt(64)

    float mx = s;
    #pragma unroll
    for (int m = 8; m >= 1; m >>= 1)
        mx = fmaxf(mx, __shfl_xor_sync(0xffffffffu, mx, m));
    float e = expf(s - mx);
    float sum = e;
    #pragma unroll
    for (int m = 8; m >= 1; m >>= 1)
        sum += __shfl_xor_sync(0xffffffffu, sum, m);
    sat[i][j] = e / sum;
    __syncthreads();

    // out[i][d] = sum_j sat[i][j] * sv[j][d]; 1024 outputs, 4 per thread
    float* orow = g_val + p * (size_t)DD;
    #pragma unroll
    for (int t = 0; t < 4; t++) {
        int idx = tid + t * 256;
        int oi = idx >> 6;
        int d  = idx & 63;
        float acc = 0.0f;
        #pragma unroll
        for (int jj = 0; jj < NHEAD; jj++)
            acc += sat[oi][jj] * sv[jj][d];
        orow[idx] = acc;
    }
}

// ---------------------------------------------------------------------------
// Launch
// Inputs (metadata order): x, W_qkv, b_qkv, W_out, b_out
// ---------------------------------------------------------------------------
extern "C" void kernel_launch(void* const* d_in, const int* in_sizes, int n_in,
                              void* d_out, int out_size)
{
    const float* x     = (const float*)d_in[0];
    const float* W_qkv = (const float*)d_in[1];
    const float* b_qkv = (const float*)d_in[2];
    const float* W_out = (const float*)d_in[3];
    const float* b_out = (const float*)d_in[4];
    float* out = (float*)d_out;

    float* qkv = nullptr;
    float* val = nullptr;
    cudaGetSymbolAddress((void**)&qkv, g_qkv);
    cudaGetSymbolAddress((void**)&val, g_val);

    // GEMM1: qkv = x @ W_qkv + b_qkv   (32768 x 3072, K=1024)
    {
        dim3 grid(N_QKV / 128, MM / 128);
        sgemm_bias_kernel<<<grid, 256>>>(x, W_qkv, b_qkv, qkv, N_QKV, DD);
    }
    // Attention per token
    attn_kernel<<<MM, 256>>>();
    // GEMM2: out = val @ W_out + b_out (32768 x 1024, K=1024)
    {
        dim3 grid(DD / 128, MM / 128);
        sgemm_bias_kernel<<<grid, 256>>>(val, W_out, b_out, out, DD, DD);
    }
}

// round 3
// speedup vs baseline: 1.4836x; 1.4836x over previous
#include <cuda_runtime.h>
#include <cuda_bf16.h>
#include <cstdint>
#include <math.h>

// Problem: B=8, S=4096, D=1024, H=16, hd=64
#define MM 32768          // B*S
#define DD 1024
#define N_QKV 3072
#define NHEAD 16
#define HDIM 64
#define KK 1024

// GEMM tiling
#define BM 128
#define BN 128
#define BK 32
#define NCHUNK (KK / BK)      // 32

// dynamic smem: two 32KB buffers, each {Ah,Al,Bh,Bl} 8KB tiles (128 rows x 64B)
#define BUF_BYTES 32768
#define OFF_AH 0
#define OFF_AL 8192
#define OFF_BH 16384
#define OFF_BL 24576
#define SMEM_DYN (2 * BUF_BYTES)

// ---------------------------------------------------------------------------
// Scratch (device globals)
// ---------------------------------------------------------------------------
__device__ float         g_qkv[(size_t)MM * N_QKV];
__device__ __nv_bfloat16 g_xhi[(size_t)MM * DD];
__device__ __nv_bfloat16 g_xlo[(size_t)MM * DD];
__device__ __nv_bfloat16 g_wqh[(size_t)N_QKV * KK];    // W_qkv^T hi  [N][K]
__device__ __nv_bfloat16 g_wql[(size_t)N_QKV * KK];
__device__ __nv_bfloat16 g_woh[(size_t)DD * KK];       // W_out^T hi
__device__ __nv_bfloat16 g_wol[(size_t)DD * KK];
__device__ __nv_bfloat16 g_vhi[(size_t)MM * DD];
__device__ __nv_bfloat16 g_vlo[(size_t)MM * DD];

// ---------------------------------------------------------------------------
// Helpers
// ---------------------------------------------------------------------------
__device__ __forceinline__ uint32_t smem_u32(const void* p) {
    uint32_t a;
    asm("{ .reg .u64 t; cvta.to.shared.u64 t, %1; cvt.u32.u64 %0, t; }"
        : "=r"(a) : "l"(p));
    return a;
}

// SW64-style swizzle on 64-byte rows: conflict-free ldmatrix
__device__ __forceinline__ uint32_t swz(uint32_t o) {
    return o ^ ((o >> 3) & 0x30);
}

__device__ __forceinline__ void cp16(uint32_t dst, const void* src) {
    asm volatile("cp.async.cg.shared.global [%0], [%1], 16;"
                 :: "r"(dst), "l"(src) : "memory");
}
__device__ __forceinline__ void cp_commit() {
    asm volatile("cp.async.commit_group;" ::: "memory");
}
template <int N>
__device__ __forceinline__ void cp_wait() {
    asm volatile("cp.async.wait_group %0;" :: "n"(N) : "memory");
}

#define LDX4(r, addr) \
    asm volatile("ldmatrix.sync.aligned.m8n8.x4.shared.b16 {%0,%1,%2,%3}, [%4];" \
        : "=r"((r)[0]), "=r"((r)[1]), "=r"((r)[2]), "=r"((r)[3]) : "r"(addr))

#define MMA16816(d, a, b) \
    asm volatile("mma.sync.aligned.m16n8k16.row.col.f32.bf16.bf16.f32 " \
        "{%0,%1,%2,%3}, {%4,%5,%6,%7}, {%8,%9}, {%0,%1,%2,%3};" \
        : "+f"((d)[0]), "+f"((d)[1]), "+f"((d)[2]), "+f"((d)[3]) \
        : "r"((a)[0]), "r"((a)[1]), "r"((a)[2]), "r"((a)[3]), \
          "r"((b)[0]), "r"((b)[1]))

// ---------------------------------------------------------------------------
// HMMA GEMM: C[M,Ntot] = (Ahi+Alo)[M,K] @ (Bhi+Blo)[Ntot,K]^T + bias
// 3-pass bf16 split, fp32 accum. 128x128 tile, BK=32, 256 threads.
// ---------------------------------------------------------------------------
__global__ __launch_bounds__(256)
void gemm_hmma(const __nv_bfloat16* __restrict__ Ahi, const __nv_bfloat16* __restrict__ Alo,
               const __nv_bfloat16* __restrict__ Bhi, const __nv_bfloat16* __restrict__ Blo,
               const float* __restrict__ bias, float* __restrict__ C, int Ntot)
{
    extern __shared__ char smem[];
    const uint32_t sb = smem_u32(smem);

    const int tid  = threadIdx.x;
    const int wid  = tid >> 5;
    const int lane = tid & 31;
    const int wm = (wid & 1) * 64;       // warp m-offset within tile
    const int wn = (wid >> 1) * 32;      // warp n-offset within tile

    const size_t m0 = (size_t)blockIdx.y * BM;
    const size_t n0 = (size_t)blockIdx.x * BN;

    // ---- precompute per-thread gmem srcs and smem dsts for cp.async ----
    // 512 x 16B chunks per operand tile; 2 per thread per operand.
    const __nv_bfloat16* srcAh[2];
    const __nv_bfloat16* srcAl[2];
    const __nv_bfloat16* srcBh[2];
    const __nv_bfloat16* srcBl[2];
    uint32_t dstOff[2];
    #pragma unroll
    for (int t = 0; t < 2; t++) {
        int idx = tid + t * 256;
        int row = idx >> 2;              // 0..127
        int cq  = idx & 3;               // 16B chunk within 64B row
        srcAh[t] = Ahi + (m0 + row) * KK + cq * 8;
        srcAl[t] = Alo + (m0 + row) * KK + cq * 8;
        srcBh[t] = Bhi + (n0 + row) * KK + cq * 8;
        srcBl[t] = Blo + (n0 + row) * KK + cq * 8;
        dstOff[t] = swz(row * 64 + cq * 16);
    }

    // ---- precompute ldmatrix offsets (per kstep: kb = 0, 32 bytes) ----
    uint32_t offA[2][4], offB[2][2];
    #pragma unroll
    for (int ks = 0; ks < 2; ks++) {
        uint32_t kb = ks * 32;
        #pragma unroll
        for (int tm = 0; tm < 4; tm++)
            offA[ks][tm] = swz((wm + tm * 16 + (lane & 15)) * 64 + kb + ((lane >> 4) << 4));
        #pragma unroll
        for (int tp = 0; tp < 2; tp++)
            offB[ks][tp] = swz((wn + tp * 16 + ((lane >> 4) & 1) * 8 + (lane & 7)) * 64
                               + kb + ((lane >> 3) & 1) * 16);
    }

    float acc[4][4][4];
    #pragma unroll
    for (int i = 0; i < 4; i++)
        #pragma unroll
        for (int j = 0; j < 4; j++)
            #pragma unroll
            for (int r = 0; r < 4; r++) acc[i][j][r] = 0.0f;

    // ---- prefetch chunk 0 into buf 0 ----
    #pragma unroll
    for (int t = 0; t < 2; t++) {
        cp16(sb + OFF_AH + dstOff[t], srcAh[t]);
        cp16(sb + OFF_AL + dstOff[t], srcAl[t]);
        cp16(sb + OFF_BH + dstOff[t], srcBh[t]);
        cp16(sb + OFF_BL + dstOff[t], srcBl[t]);
    }
    cp_commit();

    // ---- main loop ----
    #pragma unroll 1
    for (int c = 0; c < NCHUNK; ++c) {
        const uint32_t buf = sb + (uint32_t)(c & 1) * BUF_BYTES;

        if (c + 1 < NCHUNK) {
            const uint32_t nbuf = sb + (uint32_t)((c + 1) & 1) * BUF_BYTES;
            const int koff = (c + 1) * BK;
            #pragma unroll
            for (int t = 0; t < 2; t++) {
                cp16(nbuf + OFF_AH + dstOff[t], srcAh[t] + koff);
                cp16(nbuf + OFF_AL + dstOff[t], srcAl[t] + koff);
                cp16(nbuf + OFF_BH + dstOff[t], srcBh[t] + koff);
                cp16(nbuf + OFF_BL + dstOff[t], srcBl[t] + koff);
            }
            cp_commit();
            cp_wait<1>();
        } else {
            cp_wait<0>();
        }
        __syncthreads();

        #pragma unroll
        for (int ks = 0; ks < 2; ks++) {
            uint32_t ah[4][4], al[4][4], bh[4][2], bl[4][2];

            #pragma unroll
            for (int tm = 0; tm < 4; tm++)
                LDX4(ah[tm], buf + OFF_AH + offA[ks][tm]);
            #pragma unroll
            for (int tp = 0; tp < 2; tp++) {
                uint32_t r[4];
                LDX4(r, buf + OFF_BH + offB[ks][tp]);
                bh[2 * tp][0] = r[0]; bh[2 * tp][1] = r[1];
                bh[2 * tp + 1][0] = r[2]; bh[2 * tp + 1][1] = r[3];
            }
            // hi * hi
            #pragma unroll
            for (int tm = 0; tm < 4; tm++)
                #pragma unroll
                for (int tn = 0; tn < 4; tn++)
                    MMA16816(acc[tm][tn], ah[tm], bh[tn]);

            // lo * hi
            #pragma unroll
            for (int tm = 0; tm < 4; tm++)
                LDX4(al[tm], buf + OFF_AL + offA[ks][tm]);
            #pragma unroll
            for (int tm = 0; tm < 4; tm++)
                #pragma unroll
                for (int tn = 0; tn < 4; tn++)
                    MMA16816(acc[tm][tn], al[tm], bh[tn]);

            // hi * lo
            #pragma unroll
            for (int tp = 0; tp < 2; tp++) {
                uint32_t r[4];
                LDX4(r, buf + OFF_BL + offB[ks][tp]);
                bl[2 * tp][0] = r[0]; bl[2 * tp][1] = r[1];
                bl[2 * tp + 1][0] = r[2]; bl[2 * tp + 1][1] = r[3];
            }
            #pragma unroll
            for (int tm = 0; tm < 4; tm++)
                #pragma unroll
                for (int tn = 0; tn < 4; tn++)
                    MMA16816(acc[tm][tn], ah[tm], bl[tn]);
        }
        __syncthreads();
    }

    // ---- epilogue: bias + store ----
    const int rq = lane >> 2;            // 0..7
    const int cp = (lane & 3) * 2;       // 0,2,4,6
    #pragma unroll
    for (int tn = 0; tn < 4; tn++) {
        const int col = (int)n0 + wn + tn * 8 + cp;
        const float b0 = bias[col], b1 = bias[col + 1];
        #pragma unroll
        for (int tm = 0; tm < 4; tm++) {
            const size_t r1 = m0 + wm + tm * 16 + rq;
            float2 o0, o1;
            o0.x = acc[tm][tn][0] + b0;
            o0.y = acc[tm][tn][1] + b1;
            o1.x = acc[tm][tn][2] + b0;
            o1.y = acc[tm][tn][3] + b1;
            *reinterpret_cast<float2*>(C + r1 * Ntot + col) = o0;
            *reinterpret_cast<float2*>(C + (r1 + 8) * Ntot + col) = o1;
        }
    }
}

// ---------------------------------------------------------------------------
// fp32 -> bf16 hi/lo split (x)
// ---------------------------------------------------------------------------
__global__ __launch_bounds__(256)
void split_f32(const float* __restrict__ in, __nv_bfloat16* __restrict__ hi,
               __nv_bfloat16* __restrict__ lo)
{
    size_t i0 = ((size_t)blockIdx.x * 256 + threadIdx.x) * 4;
    float4 v = *reinterpret_cast<const float4*>(in + i0);
    __nv_bfloat16 h0 = __float2bfloat16(v.x), h1 = __float2bfloat16(v.y);
    __nv_bfloat16 h2 = __float2bfloat16(v.z), h3 = __float2bfloat16(v.w);
    __nv_bfloat162 ha, hb, la, lb;
    ha.x = h0; ha.y = h1; hb.x = h2; hb.y = h3;
    la.x = __float2bfloat16(v.x - __bfloat162float(h0));
    la.y = __float2bfloat16(v.y - __bfloat162float(h1));
    lb.x = __float2bfloat16(v.z - __bfloat162float(h2));
    lb.y = __float2bfloat16(v.w - __bfloat162float(h3));
    reinterpret_cast<__nv_bfloat162*>(hi + i0)[0] = ha;
    reinterpret_cast<__nv_bfloat162*>(hi + i0)[1] = hb;
    reinterpret_cast<__nv_bfloat162*>(lo + i0)[0] = la;
    reinterpret_cast<__nv_bfloat162*>(lo + i0)[1] = lb;
}

// ---------------------------------------------------------------------------
// W[K][N] fp32 -> W^T[N][K] bf16 hi/lo
// ---------------------------------------------------------------------------
__global__ __launch_bounds__(256)
void transpose_split(const float* __restrict__ W, __nv_bfloat16* __restrict__ hiT,
                     __nv_bfloat16* __restrict__ loT, int N)
{
    int k = blockIdx.x * 256 + threadIdx.x;
    int n = blockIdx.y;
    float v = W[(size_t)k * N + n];
    __nv_bfloat16 h = __float2bfloat16(v);
    hiT[(size_t)n * KK + k] = h;
    loT[(size_t)n * KK + k] = __float2bfloat16(v - __bfloat162float(h));
}

// ---------------------------------------------------------------------------
// Per-token 16x16 head attention; writes bf16 hi/lo for GEMM2's A operand
// ---------------------------------------------------------------------------
__global__ __launch_bounds__(256)
void attn_kernel()
{
    __shared__ float sq[NHEAD][HDIM];
    __shared__ float skT[HDIM][NHEAD];
    __shared__ float sv[NHEAD][HDIM];
    __shared__ float sat[NHEAD][NHEAD];

    const size_t p = blockIdx.x;
    const float* row = g_qkv + p * (size_t)N_QKV;
    const int tid = threadIdx.x;

    for (int idx = tid; idx < N_QKV; idx += 256) {
        float v = row[idx];
        int h = idx / 192;
        int r = idx - h * 192;
        if (r < 64)        sq[h][r] = v;
        else if (r < 128)  skT[r - 64][h] = v;
        else               sv[h][r - 128] = v;
    }
    __syncthreads();

    const int i = tid >> 4;
    const int j = tid & 15;
    float s = 0.0f;
    #pragma unroll 8
    for (int d = 0; d < HDIM; d++) s += sq[i][d] * skT[d][j];
    s *= 0.125f;

    float mx = s;
    #pragma unroll
    for (int m = 8; m >= 1; m >>= 1)
        mx = fmaxf(mx, __shfl_xor_sync(0xffffffffu, mx, m));
    float e = expf(s - mx);
    float sum = e;
    #pragma unroll
    for (int m = 8; m >= 1; m >>= 1)
        sum += __shfl_xor_sync(0xffffffffu, sum, m);
    sat[i][j] = e / sum;
    __syncthreads();

    __nv_bfloat16* vhi = g_vhi + p * (size_t)DD;
    __nv_bfloat16* vlo = g_vlo + p * (size_t)DD;
    #pragma unroll
    for (int t = 0; t < 4; t++) {
        int idx = tid + t * 256;
        int oi = idx >> 6;
        int d  = idx & 63;
        float acc = 0.0f;
        #pragma unroll
        for (int jj = 0; jj < NHEAD; jj++)
            acc += sat[oi][jj] * sv[jj][d];
        __nv_bfloat16 h = __float2bfloat16(acc);
        vhi[idx] = h;
        vlo[idx] = __float2bfloat16(acc - __bfloat162float(h));
    }
}

// ---------------------------------------------------------------------------
// Launch: x, W_qkv, b_qkv, W_out, b_out
// ---------------------------------------------------------------------------
extern "C" void kernel_launch(void* const* d_in, const int* in_sizes, int n_in,
                              void* d_out, int out_size)
{
    const float* x     = (const float*)d_in[0];
    const float* W_qkv = (const float*)d_in[1];
    const float* b_qkv = (const float*)d_in[2];
    const float* W_out = (const float*)d_in[3];
    const float* b_out = (const float*)d_in[4];
    float* out = (float*)d_out;

    float *qkv;
    __nv_bfloat16 *xhi, *xlo, *wqh, *wql, *woh, *wol, *vhi, *vlo;
    cudaGetSymbolAddress((void**)&qkv, g_qkv);
    cudaGetSymbolAddress((void**)&xhi, g_xhi);
    cudaGetSymbolAddress((void**)&xlo, g_xlo);
    cudaGetSymbolAddress((void**)&wqh, g_wqh);
    cudaGetSymbolAddress((void**)&wql, g_wql);
    cudaGetSymbolAddress((void**)&woh, g_woh);
    cudaGetSymbolAddress((void**)&wol, g_wol);
    cudaGetSymbolAddress((void**)&vhi, g_vhi);
    cudaGetSymbolAddress((void**)&vlo, g_vlo);

    cudaFuncSetAttribute(gemm_hmma, cudaFuncAttributeMaxDynamicSharedMemorySize, SMEM_DYN);

    // conversions
    split_f32<<<(size_t)MM * DD / (256 * 4), 256>>>(x, xhi, xlo);
    transpose_split<<<dim3(KK / 256, N_QKV), 256>>>(W_qkv, wqh, wql, N_QKV);
    transpose_split<<<dim3(KK / 256, DD), 256>>>(W_out, woh, wol, DD);

    // GEMM1: qkv = x @ W_qkv + b_qkv   (32768 x 3072, K=1024)
    gemm_hmma<<<dim3(N_QKV / BN, MM / BM), 256, SMEM_DYN>>>(
        xhi, xlo, wqh, wql, b_qkv, qkv, N_QKV);

    // attention per token
    attn_kernel<<<MM, 256>>>();

    // GEMM2: out = val @ W_out + b_out (32768 x 1024, K=1024)
    gemm_hmma<<<dim3(DD / BN, MM / BM), 256, SMEM_DYN>>>(
        vhi, vlo, woh, wol, b_out, out, DD);
}

// round 4
// speedup vs baseline: 3.8509x; 2.5956x over previous
#include <cuda_runtime.h>
#include <cuda_fp16.h>
#include <cstdint>
#include <math.h>

// Problem: B=8, S=4096, D=1024, H=16, hd=64
#define MM 32768          // B*S
#define DD 1024
#define N_QKV 3072
#define NHEAD 16
#define HDIM 64
#define KK 1024

// GEMM tiling
#define BM 128
#define BN 128
#define BK 32
#define NCHUNK (KK / BK)      // 32
#define NSTAGE 3

// smem per stage: Ahi 8KB, Alo 8KB, B 8KB
#define OFF_AH 0
#define OFF_AL 8192
#define OFF_B  16384
#define BUF_BYTES 24576
#define SMEM_DYN (NSTAGE * BUF_BYTES)     // 72 KB

// ---------------------------------------------------------------------------
// Scratch (device globals)
// ---------------------------------------------------------------------------
__device__ float  g_qkv[(size_t)MM * N_QKV];
__device__ __half g_xhi[(size_t)MM * DD];
__device__ __half g_xlo[(size_t)MM * DD];
__device__ __half g_wq[(size_t)N_QKV * KK];     // W_qkv^T  [N][K] fp16
__device__ __half g_wo[(size_t)DD * KK];        // W_out^T
__device__ __half g_vhi[(size_t)MM * DD];
__device__ __half g_vlo[(size_t)MM * DD];

// ---------------------------------------------------------------------------
// Helpers
// ---------------------------------------------------------------------------
__device__ __forceinline__ uint32_t smem_u32(const void* p) {
    uint32_t a;
    asm("{ .reg .u64 t; cvta.to.shared.u64 t, %1; cvt.u32.u64 %0, t; }"
        : "=r"(a) : "l"(p));
    return a;
}

// SW64-style swizzle on 64-byte rows (validated round 3)
__device__ __forceinline__ uint32_t swz(uint32_t o) {
    return o ^ ((o >> 3) & 0x30);
}

__device__ __forceinline__ void cp16(uint32_t dst, const void* src) {
    asm volatile("cp.async.cg.shared.global [%0], [%1], 16;"
                 :: "r"(dst), "l"(src) : "memory");
}
__device__ __forceinline__ void cp_commit() {
    asm volatile("cp.async.commit_group;" ::: "memory");
}
template <int N>
__device__ __forceinline__ void cp_wait() {
    asm volatile("cp.async.wait_group %0;" :: "n"(N) : "memory");
}

#define LDX4(r, addr) \
    asm volatile("ldmatrix.sync.aligned.m8n8.x4.shared.b16 {%0,%1,%2,%3}, [%4];" \
        : "=r"((r)[0]), "=r"((r)[1]), "=r"((r)[2]), "=r"((r)[3]) : "r"(addr))

#define MMA16816(d, a, b) \
    asm volatile("mma.sync.aligned.m16n8k16.row.col.f32.f16.f16.f32 " \
        "{%0,%1,%2,%3}, {%4,%5,%6,%7}, {%8,%9}, {%0,%1,%2,%3};" \
        : "+f"((d)[0]), "+f"((d)[1]), "+f"((d)[2]), "+f"((d)[3]) \
        : "r"((a)[0]), "r"((a)[1]), "r"((a)[2]), "r"((a)[3]), \
          "r"((b)[0]), "r"((b)[1]))

// ---------------------------------------------------------------------------
// HMMA GEMM: C[M,Ntot] = (Ahi+Alo)[M,K] @ B[Ntot,K]^T + bias
// fp16 2-pass split (A hi/lo, B single), fp32 accum.
// 128x128 tile, BK=32, 256 threads, 3-stage cp.async, 2 CTAs/SM.
// ---------------------------------------------------------------------------
__global__ __launch_bounds__(256, 2)
void gemm_hmma(const __half* __restrict__ Ahi, const __half* __restrict__ Alo,
               const __half* __restrict__ Bm,
               const float* __restrict__ bias, float* __restrict__ C, int Ntot)
{
    extern __shared__ char smem[];
    const uint32_t sb = smem_u32(smem);

    const int tid  = threadIdx.x;
    const int wid  = tid >> 5;
    const int lane = tid & 31;
    const int wm = (wid & 1) * 64;
    const int wn = (wid >> 1) * 32;

    const size_t m0 = (size_t)blockIdx.y * BM;
    const size_t n0 = (size_t)blockIdx.x * BN;

    // per-thread cp.async sources / dests (2 x 16B chunks per operand tile)
    const __half* srcAh[2];
    const __half* srcAl[2];
    const __half* srcB[2];
    uint32_t dstOff[2];
    #pragma unroll
    for (int t = 0; t < 2; t++) {
        int idx = tid + t * 256;
        int row = idx >> 2;              // 0..127
        int cq  = idx & 3;               // 16B chunk in 64B row
        srcAh[t] = Ahi + (m0 + row) * KK + cq * 8;
        srcAl[t] = Alo + (m0 + row) * KK + cq * 8;
        srcB[t]  = Bm  + (n0 + row) * KK + cq * 8;
        dstOff[t] = swz(row * 64 + cq * 16);
    }

    // ldmatrix offsets for ks=0; ks=1 is ^32 (no carry past bit 5, verified)
    uint32_t offA[4], offB[2];
    #pragma unroll
    for (int tm = 0; tm < 4; tm++)
        offA[tm] = swz((wm + tm * 16 + (lane & 15)) * 64 + ((lane >> 4) << 4));
    #pragma unroll
    for (int tp = 0; tp < 2; tp++)
        offB[tp] = swz((wn + tp * 16 + ((lane >> 4) & 1) * 8 + (lane & 7)) * 64
                       + ((lane >> 3) & 1) * 16);

    float acc[4][4][4];
    #pragma unroll
    for (int i = 0; i < 4; i++)
        #pragma unroll
        for (int j = 0; j < 4; j++)
            #pragma unroll
            for (int r = 0; r < 4; r++) acc[i][j][r] = 0.0f;

    // prefetch stages 0,1
    #pragma unroll
    for (int s = 0; s < 2; s++) {
        const uint32_t buf = sb + s * BUF_BYTES;
        const int koff = s * BK;
        #pragma unroll
        for (int t = 0; t < 2; t++) {
            cp16(buf + OFF_AH + dstOff[t], srcAh[t] + koff);
            cp16(buf + OFF_AL + dstOff[t], srcAl[t] + koff);
            cp16(buf + OFF_B  + dstOff[t], srcB[t] + koff);
        }
        cp_commit();
    }

    int bufIdx = 0;
    #pragma unroll 1
    for (int c = 0; c < NCHUNK; ++c) {
        // issue stage c+2 (or empty group to keep wait-count exact)
        if (c + 2 < NCHUNK) {
            int pidx = bufIdx + 2; if (pidx >= NSTAGE) pidx -= NSTAGE;
            const uint32_t nbuf = sb + pidx * BUF_BYTES;
            const int koff = (c + 2) * BK;
            #pragma unroll
            for (int t = 0; t < 2; t++) {
                cp16(nbuf + OFF_AH + dstOff[t], srcAh[t] + koff);
                cp16(nbuf + OFF_AL + dstOff[t], srcAl[t] + koff);
                cp16(nbuf + OFF_B  + dstOff[t], srcB[t] + koff);
            }
        }
        cp_commit();
        cp_wait<2>();
        __syncthreads();

        const uint32_t buf = sb + bufIdx * BUF_BYTES;
        #pragma unroll
        for (int ks = 0; ks < 2; ks++) {
            const uint32_t kx = ks * 32;
            uint32_t ah[4][4], al[4][4], bb[4][2];

            #pragma unroll
            for (int tm = 0; tm < 4; tm++)
                LDX4(ah[tm], buf + OFF_AH + (offA[tm] ^ kx));
            #pragma unroll
            for (int tp = 0; tp < 2; tp++) {
                uint32_t r[4];
                LDX4(r, buf + OFF_B + (offB[tp] ^ kx));
                bb[2 * tp][0] = r[0]; bb[2 * tp][1] = r[1];
                bb[2 * tp + 1][0] = r[2]; bb[2 * tp + 1][1] = r[3];
            }
            #pragma unroll
            for (int tm = 0; tm < 4; tm++)
                #pragma unroll
                for (int tn = 0; tn < 4; tn++)
                    MMA16816(acc[tm][tn], ah[tm], bb[tn]);

            #pragma unroll
            for (int tm = 0; tm < 4; tm++)
                LDX4(al[tm], buf + OFF_AL + (offA[tm] ^ kx));
            #pragma unroll
            for (int tm = 0; tm < 4; tm++)
                #pragma unroll
                for (int tn = 0; tn < 4; tn++)
                    MMA16816(acc[tm][tn], al[tm], bb[tn]);
        }
        __syncthreads();
        if (++bufIdx == NSTAGE) bufIdx = 0;
    }

    // epilogue: bias + store
    const int rq = lane >> 2;
    const int cp = (lane & 3) * 2;
    #pragma unroll
    for (int tn = 0; tn < 4; tn++) {
        const int col = (int)n0 + wn + tn * 8 + cp;
        const float b0 = bias[col], b1 = bias[col + 1];
        #pragma unroll
        for (int tm = 0; tm < 4; tm++) {
            const size_t r1 = m0 + wm + tm * 16 + rq;
            float2 o0, o1;
            o0.x = acc[tm][tn][0] + b0;
            o0.y = acc[tm][tn][1] + b1;
            o1.x = acc[tm][tn][2] + b0;
            o1.y = acc[tm][tn][3] + b1;
            *reinterpret_cast<float2*>(C + r1 * Ntot + col) = o0;
            *reinterpret_cast<float2*>(C + (r1 + 8) * Ntot + col) = o1;
        }
    }
}

// ---------------------------------------------------------------------------
// fp32 -> fp16 hi/lo split (x)
// ---------------------------------------------------------------------------
__global__ __launch_bounds__(256)
void split_f32h(const float* __restrict__ in, __half* __restrict__ hi,
                __half* __restrict__ lo)
{
    size_t i0 = ((size_t)blockIdx.x * 256 + threadIdx.x) * 4;
    float4 v = *reinterpret_cast<const float4*>(in + i0);
    __half h0 = __float2half_rn(v.x), h1 = __float2half_rn(v.y);
    __half h2 = __float2half_rn(v.z), h3 = __float2half_rn(v.w);
    __half2 ha, hb, la, lb;
    ha.x = h0; ha.y = h1; hb.x = h2; hb.y = h3;
    la.x = __float2half_rn(v.x - __half2float(h0));
    la.y = __float2half_rn(v.y - __half2float(h1));
    lb.x = __float2half_rn(v.z - __half2float(h2));
    lb.y = __float2half_rn(v.w - __half2float(h3));
    reinterpret_cast<__half2*>(hi + i0)[0] = ha;
    reinterpret_cast<__half2*>(hi + i0)[1] = hb;
    reinterpret_cast<__half2*>(lo + i0)[0] = la;
    reinterpret_cast<__half2*>(lo + i0)[1] = lb;
}

// ---------------------------------------------------------------------------
// W[K][N] fp32 -> W^T[N][K] fp16
// ---------------------------------------------------------------------------
__global__ __launch_bounds__(256)
void transpose_h(const float* __restrict__ W, __half* __restrict__ WT, int N)
{
    int k = blockIdx.x * 256 + threadIdx.x;
    int n = blockIdx.y;
    WT[(size_t)n * KK + k] = __float2half_rn(W[(size_t)k * N + n]);
}

// ---------------------------------------------------------------------------
// Per-token 16x16 head attention; writes fp16 hi/lo for GEMM2's A operand
// ---------------------------------------------------------------------------
__global__ __launch_bounds__(256)
void attn_kernel()
{
    __shared__ float sq[NHEAD][HDIM];
    __shared__ float skT[HDIM][NHEAD];
    __shared__ float sv[NHEAD][HDIM];
    __shared__ float sat[NHEAD][NHEAD];

    const size_t p = blockIdx.x;
    const float* row = g_qkv + p * (size_t)N_QKV;
    const int tid = threadIdx.x;

    for (int idx = tid; idx < N_QKV; idx += 256) {
        float v = row[idx];
        int h = idx / 192;
        int r = idx - h * 192;
        if (r < 64)        sq[h][r] = v;
        else if (r < 128)  skT[r - 64][h] = v;
        else               sv[h][r - 128] = v;
    }
    __syncthreads();

    const int i = tid >> 4;
    const int j = tid & 15;
    float s = 0.0f;
    #pragma unroll 8
    for (int d = 0; d < HDIM; d++) s += sq[i][d] * skT[d][j];
    s *= 0.125f;

    float mx = s;
    #pragma unroll
    for (int m = 8; m >= 1; m >>= 1)
        mx = fmaxf(mx, __shfl_xor_sync(0xffffffffu, mx, m));
    float e = expf(s - mx);
    float sum = e;
    #pragma unroll
    for (int m = 8; m >= 1; m >>= 1)
        sum += __shfl_xor_sync(0xffffffffu, sum, m);
    sat[i][j] = e / sum;
    __syncthreads();

    __half* vhi = g_vhi + p * (size_t)DD;
    __half* vlo = g_vlo + p * (size_t)DD;
    #pragma unroll
    for (int t = 0; t < 4; t++) {
        int idx = tid + t * 256;
        int oi = idx >> 6;
        int d  = idx & 63;
        float acc = 0.0f;
        #pragma unroll
        for (int jj = 0; jj < NHEAD; jj++)
            acc += sat[oi][jj] * sv[jj][d];
        __half h = __float2half_rn(acc);
        vhi[idx] = h;
        vlo[idx] = __float2half_rn(acc - __half2float(h));
    }
}

// ---------------------------------------------------------------------------
// Launch: x, W_qkv, b_qkv, W_out, b_out
// ---------------------------------------------------------------------------
extern "C" void kernel_launch(void* const* d_in, const int* in_sizes, int n_in,
                              void* d_out, int out_size)
{
    const float* x     = (const float*)d_in[0];
    const float* W_qkv = (const float*)d_in[1];
    const float* b_qkv = (const float*)d_in[2];
    const float* W_out = (const float*)d_in[3];
    const float* b_out = (const float*)d_in[4];
    float* out = (float*)d_out;

    float *qkv;
    __half *xhi, *xlo, *wq, *wo, *vhi, *vlo;
    cudaGetSymbolAddress((void**)&qkv, g_qkv);
    cudaGetSymbolAddress((void**)&xhi, g_xhi);
    cudaGetSymbolAddress((void**)&xlo, g_xlo);
    cudaGetSymbolAddress((void**)&wq, g_wq);
    cudaGetSymbolAddress((void**)&wo, g_wo);
    cudaGetSymbolAddress((void**)&vhi, g_vhi);
    cudaGetSymbolAddress((void**)&vlo, g_vlo);

    cudaFuncSetAttribute(gemm_hmma, cudaFuncAttributeMaxDynamicSharedMemorySize, SMEM_DYN);

    // conversions
    split_f32h<<<(size_t)MM * DD / (256 * 4), 256>>>(x, xhi, xlo);
    transpose_h<<<dim3(KK / 256, N_QKV), 256>>>(W_qkv, wq, N_QKV);
    transpose_h<<<dim3(KK / 256, DD), 256>>>(W_out, wo, DD);

    // GEMM1: qkv = x @ W_qkv + b_qkv   (32768 x 3072, K=1024)
    gemm_hmma<<<dim3(N_QKV / BN, MM / BM), 256, SMEM_DYN>>>(
        xhi, xlo, wq, b_qkv, qkv, N_QKV);

    // attention per token
    attn_kernel<<<MM, 256>>>();

    // GEMM2: out = val @ W_out + b_out (32768 x 1024, K=1024)
    gemm_hmma<<<dim3(DD / BN, MM / BM), 256, SMEM_DYN>>>(
        vhi, vlo, wo, b_out, out, DD);
}

// round 5
// speedup vs baseline: 6.3734x; 1.6550x over previous
#include <cuda_runtime.h>
#include <cuda_fp16.h>
#include <cstdint>
#include <math.h>

// Problem: B=8, S=4096, D=1024, H=16, hd=64
#define MM 32768          // B*S
#define DD 1024
#define N_QKV 3072
#define NHEAD 16
#define HDIM 64
#define KK 1024

// GEMM tiling: single-pass fp16
#define BM 128
#define BN 128
#define BK 64
#define NCHUNK (KK / BK)      // 16
#define NSTAGE 3

// smem per stage: A 16KB (128 rows x 128B), B 16KB
#define OFF_A 0
#define OFF_B 16384
#define BUF_BYTES 32768
#define SMEM_DYN (NSTAGE * BUF_BYTES)     // 96 KB

// ---------------------------------------------------------------------------
// Scratch (device globals)
// ---------------------------------------------------------------------------
__device__ float  g_qkv[(size_t)MM * N_QKV];
__device__ __half g_xh[(size_t)MM * DD];
__device__ __half g_wq[(size_t)N_QKV * KK];     // W_qkv^T  [N][K] fp16
__device__ __half g_wo[(size_t)DD * KK];        // W_out^T
__device__ __half g_vh[(size_t)MM * DD];

// ---------------------------------------------------------------------------
// Helpers
// ---------------------------------------------------------------------------
__device__ __forceinline__ uint32_t smem_u32(const void* p) {
    uint32_t a;
    asm("{ .reg .u64 t; cvta.to.shared.u64 t, %1; cvt.u32.u64 %0, t; }"
        : "=r"(a) : "l"(p));
    return a;
}

__device__ __forceinline__ void cp16(uint32_t dst, const void* src) {
    asm volatile("cp.async.cg.shared.global [%0], [%1], 16;"
                 :: "r"(dst), "l"(src) : "memory");
}
__device__ __forceinline__ void cp_commit() {
    asm volatile("cp.async.commit_group;" ::: "memory");
}
template <int N>
__device__ __forceinline__ void cp_wait() {
    asm volatile("cp.async.wait_group %0;" :: "n"(N) : "memory");
}

#define LDX4(r, addr) \
    asm volatile("ldmatrix.sync.aligned.m8n8.x4.shared.b16 {%0,%1,%2,%3}, [%4];" \
        : "=r"((r)[0]), "=r"((r)[1]), "=r"((r)[2]), "=r"((r)[3]) : "r"(addr))

#define MMA16816(d, a, b) \
    asm volatile("mma.sync.aligned.m16n8k16.row.col.f32.f16.f16.f32 " \
        "{%0,%1,%2,%3}, {%4,%5,%6,%7}, {%8,%9}, {%0,%1,%2,%3};" \
        : "+f"((d)[0]), "+f"((d)[1]), "+f"((d)[2]), "+f"((d)[3]) \
        : "r"((a)[0]), "r"((a)[1]), "r"((a)[2]), "r"((a)[3]), \
          "r"((b)[0]), "r"((b)[1]))

// ---------------------------------------------------------------------------
// HMMA GEMM (single-pass fp16): C[M,Ntot] = A[M,K] @ B[Ntot,K]^T + bias
// fp32 accum. 128x128 tile, BK=64 (128B rows, SW128 swizzle), 256 threads,
// 3-stage cp.async, 2 CTAs/SM. Warp tile 64x32 (2m x 4n warps).
// ---------------------------------------------------------------------------
__global__ __launch_bounds__(256, 2)
void gemm_hmma(const __half* __restrict__ Am, const __half* __restrict__ Bm,
               const float* __restrict__ bias, float* __restrict__ C, int Ntot)
{
    extern __shared__ char smem[];
    const uint32_t sb = smem_u32(smem);

    const int tid  = threadIdx.x;
    const int wid  = tid >> 5;
    const int lane = tid & 31;
    const int wm = (wid & 1) * 64;
    const int wn = (wid >> 1) * 32;

    const size_t m0 = (size_t)blockIdx.y * BM;
    const size_t n0 = (size_t)blockIdx.x * BN;

    // cp.async mapping: 128 rows x 128B per tile = 1024 x16B chunks; 4/thread
    const __half* srcA[4];
    const __half* srcB[4];
    uint32_t dstOff[4];
    #pragma unroll
    for (int t = 0; t < 4; t++) {
        int idx = tid + t * 256;
        int row = idx >> 3;              // 0..127
        int cq  = idx & 7;               // 16B chunk within 128B row
        srcA[t] = Am + (m0 + row) * KK + cq * 8;
        srcB[t] = Bm + (n0 + row) * KK + cq * 8;
        dstOff[t] = row * 128 + ((cq * 16) ^ ((row & 7) << 4));   // SW128
    }

    // ldmatrix offsets for ks=0; per-ks step is XOR with ks*32
    // (row base is a multiple of 128; in-row part < 128, so XOR is exact)
    uint32_t offA[4], offB[2];
    #pragma unroll
    for (int tm = 0; tm < 4; tm++) {
        int row = wm + tm * 16 + (lane & 15);
        offA[tm] = row * 128 + ((((lane >> 4) << 4)) ^ ((row & 7) << 4));
    }
    #pragma unroll
    for (int tp = 0; tp < 2; tp++) {
        int row = wn + tp * 16 + ((lane >> 4) & 1) * 8 + (lane & 7);
        offB[tp] = row * 128 + ((((lane >> 3) & 1) * 16) ^ ((row & 7) << 4));
    }

    float acc[4][4][4];
    #pragma unroll
    for (int i = 0; i < 4; i++)
        #pragma unroll
        for (int j = 0; j < 4; j++)
            #pragma unroll
            for (int r = 0; r < 4; r++) acc[i][j][r] = 0.0f;

    // prefetch stages 0,1
    #pragma unroll
    for (int s = 0; s < 2; s++) {
        const uint32_t buf = sb + s * BUF_BYTES;
        const int koff = s * BK;
        #pragma unroll
        for (int t = 0; t < 4; t++) {
            cp16(buf + OFF_A + dstOff[t], srcA[t] + koff);
            cp16(buf + OFF_B + dstOff[t], srcB[t] + koff);
        }
        cp_commit();
    }

    int bufIdx = 0;
    #pragma unroll 1
    for (int c = 0; c < NCHUNK; ++c) {
        if (c + 2 < NCHUNK) {
            int pidx = bufIdx + 2; if (pidx >= NSTAGE) pidx -= NSTAGE;
            const uint32_t nbuf = sb + pidx * BUF_BYTES;
            const int koff = (c + 2) * BK;
            #pragma unroll
            for (int t = 0; t < 4; t++) {
                cp16(nbuf + OFF_A + dstOff[t], srcA[t] + koff);
                cp16(nbuf + OFF_B + dstOff[t], srcB[t] + koff);
            }
        }
        cp_commit();
        cp_wait<2>();
        __syncthreads();

        const uint32_t buf = sb + bufIdx * BUF_BYTES;
        #pragma unroll
        for (int ks = 0; ks < 4; ks++) {
            const uint32_t kx = ks * 32;
            uint32_t aa[4][4], bb[4][2];

            #pragma unroll
            for (int tm = 0; tm < 4; tm++)
                LDX4(aa[tm], buf + OFF_A + (offA[tm] ^ kx));
            #pragma unroll
            for (int tp = 0; tp < 2; tp++) {
                uint32_t r[4];
                LDX4(r, buf + OFF_B + (offB[tp] ^ kx));
                bb[2 * tp][0] = r[0]; bb[2 * tp][1] = r[1];
                bb[2 * tp + 1][0] = r[2]; bb[2 * tp + 1][1] = r[3];
            }
            #pragma unroll
            for (int tm = 0; tm < 4; tm++)
                #pragma unroll
                for (int tn = 0; tn < 4; tn++)
                    MMA16816(acc[tm][tn], aa[tm], bb[tn]);
        }
        __syncthreads();
        if (++bufIdx == NSTAGE) bufIdx = 0;
    }

    // epilogue: bias + store
    const int rq = lane >> 2;
    const int cp = (lane & 3) * 2;
    #pragma unroll
    for (int tn = 0; tn < 4; tn++) {
        const int col = (int)n0 + wn + tn * 8 + cp;
        const float b0 = bias[col], b1 = bias[col + 1];
        #pragma unroll
        for (int tm = 0; tm < 4; tm++) {
            const size_t r1 = m0 + wm + tm * 16 + rq;
            float2 o0, o1;
            o0.x = acc[tm][tn][0] + b0;
            o0.y = acc[tm][tn][1] + b1;
            o1.x = acc[tm][tn][2] + b0;
            o1.y = acc[tm][tn][3] + b1;
            *reinterpret_cast<float2*>(C + r1 * Ntot + col) = o0;
            *reinterpret_cast<float2*>(C + (r1 + 8) * Ntot + col) = o1;
        }
    }
}

// ---------------------------------------------------------------------------
// fp32 -> fp16 convert (x)
// ---------------------------------------------------------------------------
__global__ __launch_bounds__(256)
void conv_h(const float* __restrict__ in, __half* __restrict__ hi)
{
    size_t i0 = ((size_t)blockIdx.x * 256 + threadIdx.x) * 4;
    float4 v = *reinterpret_cast<const float4*>(in + i0);
    __half2 a, b;
    a.x = __float2half_rn(v.x); a.y = __float2half_rn(v.y);
    b.x = __float2half_rn(v.z); b.y = __float2half_rn(v.w);
    reinterpret_cast<__half2*>(hi + i0)[0] = a;
    reinterpret_cast<__half2*>(hi + i0)[1] = b;
}

// ---------------------------------------------------------------------------
// W[K][N] fp32 -> W^T[N][K] fp16, tiled & coalesced
// grid (KK/32, N/32), block (32, 8)
// ---------------------------------------------------------------------------
__global__ __launch_bounds__(256)
void transpose_h(const float* __restrict__ W, __half* __restrict__ WT, int N)
{
    __shared__ float tile[32][33];
    const int k0 = blockIdx.x * 32;
    const int n0 = blockIdx.y * 32;
    const int tx = threadIdx.x, ty = threadIdx.y;
    #pragma unroll
    for (int j = 0; j < 4; j++)
        tile[ty + j * 8][tx] = W[(size_t)(k0 + ty + j * 8) * N + n0 + tx];
    __syncthreads();
    #pragma unroll
    for (int j = 0; j < 4; j++)
        WT[(size_t)(n0 + ty + j * 8) * KK + k0 + tx] =
            __float2half_rn(tile[tx][ty + j * 8]);
}

// ---------------------------------------------------------------------------
// Per-token 16x16 head attention; writes fp16 val for GEMM2's A operand
// ---------------------------------------------------------------------------
__global__ __launch_bounds__(256)
void attn_kernel()
{
    __shared__ float sq[NHEAD][HDIM];
    __shared__ float skT[HDIM][NHEAD];
    __shared__ float sv[NHEAD][HDIM];
    __shared__ float sat[NHEAD][NHEAD];

    const size_t p = blockIdx.x;
    const float* row = g_qkv + p * (size_t)N_QKV;
    const int tid = threadIdx.x;

    for (int idx = tid; idx < N_QKV; idx += 256) {
        float v = row[idx];
        int h = idx / 192;
        int r = idx - h * 192;
        if (r < 64)        sq[h][r] = v;
        else if (r < 128)  skT[r - 64][h] = v;
        else               sv[h][r - 128] = v;
    }
    __syncthreads();

    const int i = tid >> 4;
    const int j = tid & 15;
    float s = 0.0f;
    #pragma unroll 8
    for (int d = 0; d < HDIM; d++) s += sq[i][d] * skT[d][j];
    s *= 0.125f;

    float mx = s;
    #pragma unroll
    for (int m = 8; m >= 1; m >>= 1)
        mx = fmaxf(mx, __shfl_xor_sync(0xffffffffu, mx, m));
    float e = expf(s - mx);
    float sum = e;
    #pragma unroll
    for (int m = 8; m >= 1; m >>= 1)
        sum += __shfl_xor_sync(0xffffffffu, sum, m);
    sat[i][j] = e / sum;
    __syncthreads();

    __half* vh = g_vh + p * (size_t)DD;
    #pragma unroll
    for (int t = 0; t < 4; t++) {
        int idx = tid + t * 256;
        int oi = idx >> 6;
        int d  = idx & 63;
        float acc = 0.0f;
        #pragma unroll
        for (int jj = 0; jj < NHEAD; jj++)
            acc += sat[oi][jj] * sv[jj][d];
        vh[idx] = __float2half_rn(acc);
    }
}

// ---------------------------------------------------------------------------
// Launch: x, W_qkv, b_qkv, W_out, b_out
// ---------------------------------------------------------------------------
extern "C" void kernel_launch(void* const* d_in, const int* in_sizes, int n_in,
                              void* d_out, int out_size)
{
    const float* x     = (const float*)d_in[0];
    const float* W_qkv = (const float*)d_in[1];
    const float* b_qkv = (const float*)d_in[2];
    const float* W_out = (const float*)d_in[3];
    const float* b_out = (const float*)d_in[4];
    float* out = (float*)d_out;

    float *qkv;
    __half *xh, *wq, *wo, *vh;
    cudaGetSymbolAddress((void**)&qkv, g_qkv);
    cudaGetSymbolAddress((void**)&xh, g_xh);
    cudaGetSymbolAddress((void**)&wq, g_wq);
    cudaGetSymbolAddress((void**)&wo, g_wo);
    cudaGetSymbolAddress((void**)&vh, g_vh);

    cudaFuncSetAttribute(gemm_hmma, cudaFuncAttributeMaxDynamicSharedMemorySize, SMEM_DYN);

    // conversions
    conv_h<<<(size_t)MM * DD / (256 * 4), 256>>>(x, xh);
    transpose_h<<<dim3(KK / 32, N_QKV / 32), dim3(32, 8)>>>(W_qkv, wq, N_QKV);
    transpose_h<<<dim3(KK / 32, DD / 32), dim3(32, 8)>>>(W_out, wo, DD);

    // GEMM1: qkv = x @ W_qkv + b_qkv   (32768 x 3072, K=1024)
    gemm_hmma<<<dim3(N_QKV / BN, MM / BM), 256, SMEM_DYN>>>(
        xh, wq, b_qkv, qkv, N_QKV);

    // attention per token
    attn_kernel<<<MM, 256>>>();

    // GEMM2: out = val @ W_out + b_out (32768 x 1024, K=1024)
    gemm_hmma<<<dim3(DD / BN, MM / BM), 256, SMEM_DYN>>>(
        vh, wo, b_out, out, DD);
}

// round 6
// speedup vs baseline: 7.3022x; 1.1457x over previous
#include <cuda_runtime.h>
#include <cuda_fp16.h>
#include <cstdint>
#include <math.h>

// Problem: B=8, S=4096, D=1024, H=16, hd=64
#define MM 32768          // B*S
#define DD 1024
#define N_QKV 3072
#define NHEAD 16
#define HDIM 64
#define KK 1024

// GEMM tiling: single-pass fp16
#define BM 128
#define BN 128
#define BK 64
#define NCHUNK (KK / BK)      // 16
#define NSTAGE 3

// smem per stage: A 16KB (128 rows x 128B), B 16KB
#define OFF_A 0
#define OFF_B 16384
#define BUF_BYTES 32768
#define SMEM_DYN (NSTAGE * BUF_BYTES)     // 96 KB

// ---------------------------------------------------------------------------
// Scratch (device globals)
// ---------------------------------------------------------------------------
__device__ __half g_qkvh[(size_t)MM * N_QKV];   // fp16 qkv
__device__ __half g_xh[(size_t)MM * DD];
__device__ __half g_wq[(size_t)N_QKV * KK];     // W_qkv^T  [N][K] fp16
__device__ __half g_wo[(size_t)DD * KK];        // W_out^T
__device__ __half g_vh[(size_t)MM * DD];

// ---------------------------------------------------------------------------
// Helpers
// ---------------------------------------------------------------------------
__device__ __forceinline__ uint32_t smem_u32(const void* p) {
    uint32_t a;
    asm("{ .reg .u64 t; cvta.to.shared.u64 t, %1; cvt.u32.u64 %0, t; }"
        : "=r"(a) : "l"(p));
    return a;
}

__device__ __forceinline__ void cp16(uint32_t dst, const void* src) {
    asm volatile("cp.async.cg.shared.global [%0], [%1], 16;"
                 :: "r"(dst), "l"(src) : "memory");
}
__device__ __forceinline__ void cp_commit() {
    asm volatile("cp.async.commit_group;" ::: "memory");
}
template <int N>
__device__ __forceinline__ void cp_wait() {
    asm volatile("cp.async.wait_group %0;" :: "n"(N) : "memory");
}

#define LDX4(r, addr) \
    asm volatile("ldmatrix.sync.aligned.m8n8.x4.shared.b16 {%0,%1,%2,%3}, [%4];" \
        : "=r"((r)[0]), "=r"((r)[1]), "=r"((r)[2]), "=r"((r)[3]) : "r"(addr))

#define MMA16816(d, a, b) \
    asm volatile("mma.sync.aligned.m16n8k16.row.col.f32.f16.f16.f32 " \
        "{%0,%1,%2,%3}, {%4,%5,%6,%7}, {%8,%9}, {%0,%1,%2,%3};" \
        : "+f"((d)[0]), "+f"((d)[1]), "+f"((d)[2]), "+f"((d)[3]) \
        : "r"((a)[0]), "r"((a)[1]), "r"((a)[2]), "r"((a)[3]), \
          "r"((b)[0]), "r"((b)[1]))

// ---------------------------------------------------------------------------
// HMMA GEMM (single-pass fp16): C[M,Ntot] = A[M,K] @ B[Ntot,K]^T + bias
// fp32 accum, OutT output (half for GEMM1, float for GEMM2).
// 128x128 tile, BK=64 (128B rows, SW128 swizzle), 256 threads,
// 3-stage cp.async, 2 CTAs/SM. Warp tile 64x32 (2m x 4n warps).
// ---------------------------------------------------------------------------
template <typename OutT>
__global__ __launch_bounds__(256, 2)
void gemm_hmma(const __half* __restrict__ Am, const __half* __restrict__ Bm,
               const float* __restrict__ bias, OutT* __restrict__ C, int Ntot)
{
    extern __shared__ char smem[];
    const uint32_t sb = smem_u32(smem);

    const int tid  = threadIdx.x;
    const int wid  = tid >> 5;
    const int lane = tid & 31;
    const int wm = (wid & 1) * 64;
    const int wn = (wid >> 1) * 32;

    const size_t m0 = (size_t)blockIdx.y * BM;
    const size_t n0 = (size_t)blockIdx.x * BN;

    // cp.async mapping: 128 rows x 128B per tile = 1024 x16B chunks; 4/thread
    const __half* srcA[4];
    const __half* srcB[4];
    uint32_t dstOff[4];
    #pragma unroll
    for (int t = 0; t < 4; t++) {
        int idx = tid + t * 256;
        int row = idx >> 3;              // 0..127
        int cq  = idx & 7;               // 16B chunk within 128B row
        srcA[t] = Am + (m0 + row) * KK + cq * 8;
        srcB[t] = Bm + (n0 + row) * KK + cq * 8;
        dstOff[t] = row * 128 + ((cq * 16) ^ ((row & 7) << 4));   // SW128
    }

    // ldmatrix offsets for ks=0; per-ks step is XOR with ks*32
    uint32_t offA[4], offB[2];
    #pragma unroll
    for (int tm = 0; tm < 4; tm++) {
        int row = wm + tm * 16 + (lane & 15);
        offA[tm] = row * 128 + ((((lane >> 4) << 4)) ^ ((row & 7) << 4));
    }
    #pragma unroll
    for (int tp = 0; tp < 2; tp++) {
        int row = wn + tp * 16 + ((lane >> 4) & 1) * 8 + (lane & 7);
        offB[tp] = row * 128 + ((((lane >> 3) & 1) * 16) ^ ((row & 7) << 4));
    }

    float acc[4][4][4];
    #pragma unroll
    for (int i = 0; i < 4; i++)
        #pragma unroll
        for (int j = 0; j < 4; j++)
            #pragma unroll
            for (int r = 0; r < 4; r++) acc[i][j][r] = 0.0f;

    // prefetch stages 0,1
    #pragma unroll
    for (int s = 0; s < 2; s++) {
        const uint32_t buf = sb + s * BUF_BYTES;
        const int koff = s * BK;
        #pragma unroll
        for (int t = 0; t < 4; t++) {
            cp16(buf + OFF_A + dstOff[t], srcA[t] + koff);
            cp16(buf + OFF_B + dstOff[t], srcB[t] + koff);
        }
        cp_commit();
    }

    int bufIdx = 0;
    #pragma unroll 1
    for (int c = 0; c < NCHUNK; ++c) {
        if (c + 2 < NCHUNK) {
            int pidx = bufIdx + 2; if (pidx >= NSTAGE) pidx -= NSTAGE;
            const uint32_t nbuf = sb + pidx * BUF_BYTES;
            const int koff = (c + 2) * BK;
            #pragma unroll
            for (int t = 0; t < 4; t++) {
                cp16(nbuf + OFF_A + dstOff[t], srcA[t] + koff);
                cp16(nbuf + OFF_B + dstOff[t], srcB[t] + koff);
            }
        }
        cp_commit();
        cp_wait<2>();
        __syncthreads();

        const uint32_t buf = sb + bufIdx * BUF_BYTES;
        #pragma unroll
        for (int ks = 0; ks < 4; ks++) {
            const uint32_t kx = ks * 32;
            uint32_t aa[4][4], bb[4][2];

            #pragma unroll
            for (int tm = 0; tm < 4; tm++)
                LDX4(aa[tm], buf + OFF_A + (offA[tm] ^ kx));
            #pragma unroll
            for (int tp = 0; tp < 2; tp++) {
                uint32_t r[4];
                LDX4(r, buf + OFF_B + (offB[tp] ^ kx));
                bb[2 * tp][0] = r[0]; bb[2 * tp][1] = r[1];
                bb[2 * tp + 1][0] = r[2]; bb[2 * tp + 1][1] = r[3];
            }
            #pragma unroll
            for (int tm = 0; tm < 4; tm++)
                #pragma unroll
                for (int tn = 0; tn < 4; tn++)
                    MMA16816(acc[tm][tn], aa[tm], bb[tn]);
        }
        __syncthreads();
        if (++bufIdx == NSTAGE) bufIdx = 0;
    }

    // epilogue: bias + store (fp32 or fp16 output)
    const int rq = lane >> 2;
    const int cp = (lane & 3) * 2;
    #pragma unroll
    for (int tn = 0; tn < 4; tn++) {
        const int col = (int)n0 + wn + tn * 8 + cp;
        const float b0 = bias[col], b1 = bias[col + 1];
        #pragma unroll
        for (int tm = 0; tm < 4; tm++) {
            const size_t r1 = m0 + wm + tm * 16 + rq;
            float2 o0, o1;
            o0.x = acc[tm][tn][0] + b0;
            o0.y = acc[tm][tn][1] + b1;
            o1.x = acc[tm][tn][2] + b0;
            o1.y = acc[tm][tn][3] + b1;
            if constexpr (sizeof(OutT) == 4) {
                *reinterpret_cast<float2*>((float*)C + r1 * Ntot + col) = o0;
                *reinterpret_cast<float2*>((float*)C + (r1 + 8) * Ntot + col) = o1;
            } else {
                *reinterpret_cast<__half2*>((__half*)C + r1 * Ntot + col) =
                    __floats2half2_rn(o0.x, o0.y);
                *reinterpret_cast<__half2*>((__half*)C + (r1 + 8) * Ntot + col) =
                    __floats2half2_rn(o1.x, o1.y);
            }
        }
    }
}

// ---------------------------------------------------------------------------
// fp32 -> fp16 convert (x)
// ---------------------------------------------------------------------------
__global__ __launch_bounds__(256)
void conv_h(const float* __restrict__ in, __half* __restrict__ hi)
{
    size_t i0 = ((size_t)blockIdx.x * 256 + threadIdx.x) * 4;
    float4 v = *reinterpret_cast<const float4*>(in + i0);
    __half2 a, b;
    a.x = __float2half_rn(v.x); a.y = __float2half_rn(v.y);
    b.x = __float2half_rn(v.z); b.y = __float2half_rn(v.w);
    reinterpret_cast<__half2*>(hi + i0)[0] = a;
    reinterpret_cast<__half2*>(hi + i0)[1] = b;
}

// ---------------------------------------------------------------------------
// W[K][N] fp32 -> W^T[N][K] fp16, tiled & coalesced
// ---------------------------------------------------------------------------
__global__ __launch_bounds__(256)
void transpose_h(const float* __restrict__ W, __half* __restrict__ WT, int N)
{
    __shared__ float tile[32][33];
    const int k0 = blockIdx.x * 32;
    const int n0 = blockIdx.y * 32;
    const int tx = threadIdx.x, ty = threadIdx.y;
    #pragma unroll
    for (int j = 0; j < 4; j++)
        tile[ty + j * 8][tx] = W[(size_t)(k0 + ty + j * 8) * N + n0 + tx];
    __syncthreads();
    #pragma unroll
    for (int j = 0; j < 4; j++)
        WT[(size_t)(n0 + ty + j * 8) * KK + k0 + tx] =
            __float2half_rn(tile[tx][ty + j * 8]);
}

// ---------------------------------------------------------------------------
// Per-token 16x16 head attention (fp16 qkv in, fp16 val out).
// 256 threads per token. half2 loads; skT padded for conflict-free stores.
// ---------------------------------------------------------------------------
__global__ __launch_bounds__(256)
void attn_kernel()
{
    __shared__ float sq[NHEAD][HDIM];
    __shared__ float skT[HDIM][NHEAD + 1];
    __shared__ float sv[NHEAD][HDIM];
    __shared__ float sat[NHEAD][NHEAD];

    const size_t p = blockIdx.x;
    const __half2* row2 = reinterpret_cast<const __half2*>(g_qkvh + p * (size_t)N_QKV);
    const int tid = threadIdx.x;

    // 1536 half2 per token; 6 per thread
    #pragma unroll
    for (int t = 0; t < 6; t++) {
        int i2 = tid + t * 256;
        float2 f = __half22float2(row2[i2]);
        int h = i2 / 96;                 // 96 half2 per head
        int r = 2 * (i2 - h * 96);       // 0..190, even
        if (r < 64) {
            sq[h][r] = f.x; sq[h][r + 1] = f.y;
        } else if (r < 128) {
            int rr = r - 64;
            skT[rr][h] = f.x; skT[rr + 1][h] = f.y;
        } else {
            int rr = r - 128;
            sv[h][rr] = f.x; sv[h][rr + 1] = f.y;
        }
    }
    __syncthreads();

    const int i = tid >> 4;
    const int j = tid & 15;
    float s = 0.0f;
    #pragma unroll 8
    for (int d = 0; d < HDIM; d++) s += sq[i][d] * skT[d][j];
    s *= 0.125f;

    float mx = s;
    #pragma unroll
    for (int m = 8; m >= 1; m >>= 1)
        mx = fmaxf(mx, __shfl_xor_sync(0xffffffffu, mx, m));
    float e = __expf(s - mx);
    float sum = e;
    #pragma unroll
    for (int m = 8; m >= 1; m >>= 1)
        sum += __shfl_xor_sync(0xffffffffu, sum, m);
    sat[i][j] = e / sum;
    __syncthreads();

    // out[i][d] = sum_j sat[i][j] * sv[j][d]; 512 half2 outputs, 2/thread
    __half2* vh2 = reinterpret_cast<__half2*>(g_vh + p * (size_t)DD);
    #pragma unroll
    for (int t = 0; t < 2; t++) {
        int i2 = tid + t * 256;
        int oi = i2 >> 5;                // 32 half2 per output row
        int d  = (i2 & 31) * 2;
        float a0 = 0.0f, a1 = 0.0f;
        #pragma unroll
        for (int jj = 0; jj < NHEAD; jj++) {
            float w = sat[oi][jj];
            a0 += w * sv[jj][d];
            a1 += w * sv[jj][d + 1];
        }
        vh2[i2] = __floats2half2_rn(a0, a1);
    }
}

// ---------------------------------------------------------------------------
// Launch: x, W_qkv, b_qkv, W_out, b_out
// ---------------------------------------------------------------------------
extern "C" void kernel_launch(void* const* d_in, const int* in_sizes, int n_in,
                              void* d_out, int out_size)
{
    const float* x     = (const float*)d_in[0];
    const float* W_qkv = (const float*)d_in[1];
    const float* b_qkv = (const float*)d_in[2];
    const float* W_out = (const float*)d_in[3];
    const float* b_out = (const float*)d_in[4];
    float* out = (float*)d_out;

    __half *qkvh, *xh, *wq, *wo, *vh;
    cudaGetSymbolAddress((void**)&qkvh, g_qkvh);
    cudaGetSymbolAddress((void**)&xh, g_xh);
    cudaGetSymbolAddress((void**)&wq, g_wq);
    cudaGetSymbolAddress((void**)&wo, g_wo);
    cudaGetSymbolAddress((void**)&vh, g_vh);

    cudaFuncSetAttribute(gemm_hmma<__half>,
                         cudaFuncAttributeMaxDynamicSharedMemorySize, SMEM_DYN);
    cudaFuncSetAttribute(gemm_hmma<float>,
                         cudaFuncAttributeMaxDynamicSharedMemorySize, SMEM_DYN);

    // conversions
    conv_h<<<(size_t)MM * DD / (256 * 4), 256>>>(x, xh);
    transpose_h<<<dim3(KK / 32, N_QKV / 32), dim3(32, 8)>>>(W_qkv, wq, N_QKV);
    transpose_h<<<dim3(KK / 32, DD / 32), dim3(32, 8)>>>(W_out, wo, DD);

    // GEMM1: qkv(fp16) = x @ W_qkv + b_qkv   (32768 x 3072, K=1024)
    gemm_hmma<__half><<<dim3(N_QKV / BN, MM / BM), 256, SMEM_DYN>>>(
        xh, wq, b_qkv, qkvh, N_QKV);

    // attention per token
    attn_kernel<<<MM, 256>>>();

    // GEMM2: out = val @ W_out + b_out (32768 x 1024, K=1024)
    gemm_hmma<float><<<dim3(DD / BN, MM / BM), 256, SMEM_DYN>>>(
        vh, wo, b_out, out, DD);
}